// round 4
// baseline (speedup 1.0000x reference)
#include <cuda_runtime.h>
#include <cstdint>
#include <cstddef>

#define DIM       8192
#define BATCH     8
#define TOPK      60
#define SLICES    16
#define SLICE_LEN 512              // DIM / SLICES
#define NCAND     (SLICES * TOPK)  // 960 candidates per row

// ---------------- scratch (device globals; no allocation allowed) ----------
__device__ float g_act1 [BATCH * DIM];
__device__ float g_act2 [BATCH * DIM];
__device__ float g_candv[BATCH * NCAND];
__device__ int   g_candi[BATCH * NCAND];
__device__ float g_vals [BATCH * TOPK];
__device__ int   g_idx  [BATCH * TOPK];

typedef unsigned long long u64;

__device__ __forceinline__ void fma2(u64& d, u64 a, u64 b) {
    asm volatile("fma.rn.f32x2 %0, %1, %2, %0;" : "+l"(d) : "l"(a), "l"(b));
}
__device__ __forceinline__ float sigmoidf_(float x) {
    return 1.0f / (1.0f + __expf(-x));
}
__device__ __forceinline__ float pairsum(u64 a) {
    return __uint_as_float((unsigned)(a & 0xffffffffull)) +
           __uint_as_float((unsigned)(a >> 32));
}
__device__ __forceinline__ void cp_async16(void* sptr, const void* gptr) {
    unsigned s = (unsigned)__cvta_generic_to_shared(sptr);
    asm volatile("cp.async.cg.shared.global [%0], [%1], 16;" :: "r"(s), "l"(gptr));
}
__device__ __forceinline__ void cp_commit() { asm volatile("cp.async.commit_group;"); }
__device__ __forceinline__ void cp_wait1()  { asm volatile("cp.async.wait_group 1;"); }
__device__ __forceinline__ void cp_wait0()  { asm volatile("cp.async.wait_group 0;"); }

// ---------------------------------------------------------------------------
// GEMM1 (raw sums): out[b][j] = sum_i sdr[b][i] * syn[j][i]
// 256 threads (8 warps), 4 rows/warp -> 32-row j-tile, grid = 256.
// K split into 16 chunks of 512; sdr chunk (8x512 fl = 16KB) staged via
// cp.async into a double buffer, prefetching chunk c+1 during compute of c.
// Packed f32x2 FMA over K-pairs. Synapse streamed with 16B loads.
// ---------------------------------------------------------------------------
__global__ __launch_bounds__(256, 2) void gemm1_kernel(
    const float* __restrict__ sdr,
    const float* __restrict__ syn,
    float* __restrict__ out)
{
    __shared__ float4 sbuf[2][BATCH * 128];   // 2 x 16 KB

    const int tid  = threadIdx.x;
    const int warp = tid >> 5;
    const int lane = tid & 31;
    const int jBase = blockIdx.x * 32 + warp * 4;

    const float4* __restrict__ sdr4 = reinterpret_cast<const float4*>(sdr);
    const float4* __restrict__ syn4 = reinterpret_cast<const float4*>(syn);
    const int ROW4 = DIM / 4;                 // 2048 float4 per row

    u64 acc[4][BATCH];
#pragma unroll
    for (int r = 0; r < 4; ++r)
#pragma unroll
        for (int b = 0; b < BATCH; ++b) acc[r][b] = 0ull;

    // prologue: stage chunk 0 into buffer 0
#pragma unroll
    for (int u = 0; u < 4; ++u) {
        int e = tid + u * 256;                // 0..1023
        int b = e >> 7, q = e & 127;
        cp_async16(&sbuf[0][b * 128 + q], &sdr4[(size_t)b * ROW4 + q]);
    }
    cp_commit();

    for (int c = 0; c < 16; ++c) {
        if (c + 1 < 16) {                     // prefetch chunk c+1
            const int nb = (c + 1) & 1;
#pragma unroll
            for (int u = 0; u < 4; ++u) {
                int e = tid + u * 256;
                int b = e >> 7, q = e & 127;
                cp_async16(&sbuf[nb][b * 128 + q],
                           &sdr4[(size_t)b * ROW4 + (c + 1) * 128 + q]);
            }
            cp_commit();
            cp_wait1();                       // chunk c complete (c+1 may fly)
        } else {
            cp_wait0();
        }
        __syncthreads();

        const float4* sb = sbuf[c & 1];
#pragma unroll 2
        for (int it = 0; it < 4; ++it) {
            const int pos = it * 32 + lane;
            float4 w[4];
#pragma unroll
            for (int r = 0; r < 4; ++r)
                w[r] = syn4[(size_t)(jBase + r) * ROW4 + c * 128 + pos];

#pragma unroll
            for (int b = 0; b < BATCH; ++b) {
                float4 s = sb[b * 128 + pos];
                u64 sx = *reinterpret_cast<u64*>(&s.x);
                u64 sz = *reinterpret_cast<u64*>(&s.z);
#pragma unroll
                for (int r = 0; r < 4; ++r) {
                    fma2(acc[r][b], sx, *reinterpret_cast<u64*>(&w[r].x));
                    fma2(acc[r][b], sz, *reinterpret_cast<u64*>(&w[r].z));
                }
            }
        }
        __syncthreads();                      // buf (c&1) free for chunk c+2
    }

    // reduce: 32 (r,b) pairs, butterfly each, writer lane = r*8+b
#pragma unroll
    for (int r = 0; r < 4; ++r) {
#pragma unroll
        for (int b = 0; b < BATCH; ++b) {
            float v = pairsum(acc[r][b]);
#pragma unroll
            for (int o = 16; o > 0; o >>= 1)
                v += __shfl_xor_sync(0xffffffffu, v, o);
            if (lane == r * 8 + b)
                out[(size_t)b * DIM + jBase + r] = v;
        }
    }
}

// ---------------------------------------------------------------------------
// Top-k phase A: local exact top-60 per 512-wide slice via rank-by-broadcast.
// rank(v) = #{i : v_i > v} + #{i < me : v_i == v}  (jax tie order: low idx).
// Global top-60 under this total order is contained in union of slice top-60s.
// grid = (16 slices, 8 rows), block = 512. Writes rank-ordered candidates.
// ---------------------------------------------------------------------------
__global__ __launch_bounds__(512) void topk_local(
    const float* __restrict__ act,
    float* __restrict__ candv,
    int*   __restrict__ candi)
{
    __shared__ float sv[SLICE_LEN];
    const int row   = blockIdx.y;
    const int slice = blockIdx.x;
    const int tid   = threadIdx.x;

    const float v = act[(size_t)row * DIM + slice * SLICE_LEN + tid];
    sv[tid] = v;
    __syncthreads();

    int rank = 0;
    const float4* sv4 = reinterpret_cast<const float4*>(sv);
#pragma unroll 4
    for (int i4 = 0; i4 < SLICE_LEN / 4; ++i4) {
        float4 u = sv4[i4];
        int i = i4 * 4;
        rank += (u.x > v) || (u.x == v && (i + 0) < tid);
        rank += (u.y > v) || (u.y == v && (i + 1) < tid);
        rank += (u.z > v) || (u.z == v && (i + 2) < tid);
        rank += (u.w > v) || (u.w == v && (i + 3) < tid);
    }
    if (rank < TOPK) {
        int o = (row * SLICES + slice) * TOPK + rank;
        candv[o] = v;
        candi[o] = slice * SLICE_LEN + tid;
    }
}

// ---------------------------------------------------------------------------
// Top-k phase B: exact merge of 960 candidates per row by rank-by-broadcast
// under (value desc, global index asc). Emits compact sigmoid'd lists and/or
// a dense zero-filled sigmoid'd row. grid = 8 rows, block = 1024.
// ---------------------------------------------------------------------------
__global__ __launch_bounds__(1024) void topk_merge(
    const float* __restrict__ candv,
    const int*   __restrict__ candi,
    float* __restrict__ vals,     // compact values (or nullptr)
    int*   __restrict__ idxs,     // compact indices (or nullptr)
    float* __restrict__ dense)    // dense zero-filled output (or nullptr)
{
    __shared__ float sv[NCAND];
    __shared__ int   si[NCAND];
    const int row = blockIdx.x;
    const int tid = threadIdx.x;

    if (tid < NCAND) {
        sv[tid] = candv[row * NCAND + tid];
        si[tid] = candi[row * NCAND + tid];
    }
    if (dense) {                               // zero-fill this row
        float4* d4 = reinterpret_cast<float4*>(dense + (size_t)row * DIM);
        for (int q = tid; q < DIM / 4; q += 1024)
            d4[q] = make_float4(0.f, 0.f, 0.f, 0.f);
    }
    __syncthreads();

    if (tid < NCAND) {
        const float v  = sv[tid];
        const int   gi = si[tid];
        int rank = 0;
#pragma unroll 4
        for (int i = 0; i < NCAND; ++i) {
            float u = sv[i];
            rank += (u > v) || (u == v && si[i] < gi);
        }
        if (rank < TOPK) {
            float s = sigmoidf_(v);
            if (vals)  { vals[row * TOPK + rank] = s; idxs[row * TOPK + rank] = gi; }
            if (dense) dense[(size_t)row * DIM + gi] = s;
        }
    }
}

// ---------------------------------------------------------------------------
// GEMM2 (sparse, raw): out[b][j] = sum_s v[b][s] * syn[j][idx[b][s]]
// Thread = (j lane, b). Block = 32 j x 8 b; grid = 256 blocks.
// 60 independent gathered loads/thread. ~126 MB effective DRAM traffic.
// ---------------------------------------------------------------------------
__global__ __launch_bounds__(256) void gemm2_kernel(
    const float* __restrict__ syn,
    const float* __restrict__ vals,
    const int*   __restrict__ idxs,
    float* __restrict__ out)
{
    __shared__ float sv[BATCH][TOPK];
    __shared__ int   si[BATCH][TOPK];

    const int tx = threadIdx.x;   // 0..31 (j)
    const int b  = threadIdx.y;   // 0..7
    const int t  = b * 32 + tx;

    for (int u = t; u < BATCH * TOPK; u += 256) {
        int bb = u / TOPK, ss = u % TOPK;
        sv[bb][ss] = vals[bb * TOPK + ss];
        si[bb][ss] = idxs[bb * TOPK + ss];
    }
    __syncthreads();

    const int j = blockIdx.x * 32 + tx;
    const float* __restrict__ wrow = syn + (size_t)j * DIM;

    float acc = 0.0f;
#pragma unroll
    for (int s = 0; s < TOPK; ++s)
        acc += sv[b][s] * __ldg(wrow + si[b][s]);

    out[(size_t)b * DIM + j] = acc;
}

// ---------------------------------------------------------------------------
extern "C" void kernel_launch(void* const* d_in, const int* in_sizes, int n_in,
                              void* d_out, int out_size)
{
    const float* sdr = (const float*)d_in[0];
    const float* syn = (const float*)d_in[1];
    // steps=2, top_k=60 fixed by setup_inputs (hardcoded)

    float *act1, *act2, *candv, *vals;
    int *candi, *idx;
    cudaGetSymbolAddress((void**)&act1,  g_act1);
    cudaGetSymbolAddress((void**)&act2,  g_act2);
    cudaGetSymbolAddress((void**)&candv, g_candv);
    cudaGetSymbolAddress((void**)&candi, g_candi);
    cudaGetSymbolAddress((void**)&vals,  g_vals);
    cudaGetSymbolAddress((void**)&idx,   g_idx);

    // step 1: dense GEMM (raw sums) -> exact top-60 -> compact sigmoid'd lists
    gemm1_kernel<<<DIM / 32, 256>>>(sdr, syn, act1);
    topk_local<<<dim3(SLICES, BATCH), SLICE_LEN>>>(act1, candv, candi);
    topk_merge<<<BATCH, 1024>>>(candv, candi, vals, idx, nullptr);

    // step 2: sparse GEMM (raw sums) -> exact top-60 -> dense sigmoid'd output
    gemm2_kernel<<<DIM / 32, dim3(32, 8)>>>(syn, vals, idx, act2);
    topk_local<<<dim3(SLICES, BATCH), SLICE_LEN>>>(act2, candv, candi);
    topk_merge<<<BATCH, 1024>>>(candv, candi, nullptr, nullptr, (float*)d_out);
}

// round 5
// speedup vs baseline: 1.0505x; 1.0505x over previous
#include <cuda_runtime.h>
#include <cstdint>
#include <cstddef>

#define DIM       8192
#define BATCH     8
#define TOPK      60
#define SLICES    16
#define SLICE_LEN 512              // DIM / SLICES
#define NCAND     (SLICES * TOPK)  // 960 candidates per row

// ---------------- scratch (device globals; no allocation allowed) ----------
__device__ float g_act1 [BATCH * DIM];
__device__ float g_act2 [BATCH * DIM];
__device__ float g_candv[BATCH * NCAND];
__device__ int   g_candi[BATCH * NCAND];
__device__ float g_vals [BATCH * TOPK];
__device__ int   g_idx  [BATCH * TOPK];

typedef unsigned long long u64;

__device__ __forceinline__ void fma2(u64& d, u64 a, u64 b) {
    asm volatile("fma.rn.f32x2 %0, %1, %2, %0;" : "+l"(d) : "l"(a), "l"(b));
}
__device__ __forceinline__ float sigmoidf_(float x) {
    return 1.0f / (1.0f + __expf(-x));
}
__device__ __forceinline__ float pairsum(u64 a) {
    return __uint_as_float((unsigned)(a & 0xffffffffull)) +
           __uint_as_float((unsigned)(a >> 32));
}

// ---------------------------------------------------------------------------
// GEMM1 (raw sums) — R3-proven version (46 us, at achieved-BW roofline).
// 256 threads (8 warps), 4 rows/warp -> 32-row j-tile, grid = 256.
// K split into 8 chunks of 1024; sdr chunk (8x1024 fl = 32KB) staged in SMEM,
// then barrier-free inner loop streams synapse rows. Packed f32x2 FMA.
// ---------------------------------------------------------------------------
__global__ __launch_bounds__(256, 2) void gemm1_kernel(
    const float* __restrict__ sdr,
    const float* __restrict__ syn,
    float* __restrict__ out)
{
    __shared__ float4 s_sdr[BATCH * 256];     // 8 x 1024 floats = 32 KB

    const int tid  = threadIdx.x;
    const int warp = tid >> 5;
    const int lane = tid & 31;
    const int jBase = blockIdx.x * 32 + warp * 4;

    const float4* __restrict__ sdr4 = reinterpret_cast<const float4*>(sdr);
    const float4* __restrict__ syn4 = reinterpret_cast<const float4*>(syn);
    const int ROW4 = DIM / 4;                 // 2048 float4 per row

    u64 acc[4][BATCH];
#pragma unroll
    for (int r = 0; r < 4; ++r)
#pragma unroll
        for (int b = 0; b < BATCH; ++b) acc[r][b] = 0ull;

    for (int c = 0; c < 8; ++c) {             // 8 chunks of 1024 floats
        __syncthreads();
        // stage sdr chunk: 8 b x 256 float4 = 2048 float4, 8 per thread
#pragma unroll
        for (int u = 0; u < 8; ++u) {
            int e = tid + u * 256;            // 0..2047
            int b = e >> 8, q = e & 255;
            s_sdr[b * 256 + q] = sdr4[(size_t)b * ROW4 + c * 256 + q];
        }
        __syncthreads();

#pragma unroll 2
        for (int it = 0; it < 8; ++it) {      // 256 float4 / 32 lanes
            const int pos = it * 32 + lane;
            float4 w[4];
#pragma unroll
            for (int r = 0; r < 4; ++r)
                w[r] = syn4[(size_t)(jBase + r) * ROW4 + c * 256 + pos];

#pragma unroll
            for (int b = 0; b < BATCH; ++b) {
                float4 s = s_sdr[b * 256 + pos];
                u64 sx = *reinterpret_cast<u64*>(&s.x);
                u64 sz = *reinterpret_cast<u64*>(&s.z);
#pragma unroll
                for (int r = 0; r < 4; ++r) {
                    fma2(acc[r][b], sx, *reinterpret_cast<u64*>(&w[r].x));
                    fma2(acc[r][b], sz, *reinterpret_cast<u64*>(&w[r].z));
                }
            }
        }
    }

    // reduce: 32 (r,b) pairs, butterfly each, writer lane = r*8+b
#pragma unroll
    for (int r = 0; r < 4; ++r) {
#pragma unroll
        for (int b = 0; b < BATCH; ++b) {
            float v = pairsum(acc[r][b]);
#pragma unroll
            for (int o = 16; o > 0; o >>= 1)
                v += __shfl_xor_sync(0xffffffffu, v, o);
            if (lane == r * 8 + b)
                out[(size_t)b * DIM + jBase + r] = v;
        }
    }
}

// ---------------------------------------------------------------------------
// Top-k phase A: local exact top-60 per 512-wide slice via rank-by-broadcast.
// rank(v) = #{i : v_i > v} + #{i < me : v_i == v}  (jax tie order: low idx).
// Global top-60 under this total order is contained in union of slice top-60s.
// grid = (16 slices, 8 rows), block = 512. Writes rank-ordered candidates.
// ---------------------------------------------------------------------------
__global__ __launch_bounds__(512) void topk_local(
    const float* __restrict__ act,
    float* __restrict__ candv,
    int*   __restrict__ candi)
{
    __shared__ float sv[SLICE_LEN];
    const int row   = blockIdx.y;
    const int slice = blockIdx.x;
    const int tid   = threadIdx.x;

    const float v = act[(size_t)row * DIM + slice * SLICE_LEN + tid];
    sv[tid] = v;
    __syncthreads();

    int rank = 0;
    const float4* sv4 = reinterpret_cast<const float4*>(sv);
#pragma unroll 4
    for (int i4 = 0; i4 < SLICE_LEN / 4; ++i4) {
        float4 u = sv4[i4];
        int i = i4 * 4;
        rank += (u.x > v) || (u.x == v && (i + 0) < tid);
        rank += (u.y > v) || (u.y == v && (i + 1) < tid);
        rank += (u.z > v) || (u.z == v && (i + 2) < tid);
        rank += (u.w > v) || (u.w == v && (i + 3) < tid);
    }
    if (rank < TOPK) {
        int o = (row * SLICES + slice) * TOPK + rank;
        candv[o] = v;
        candi[o] = slice * SLICE_LEN + tid;
    }
}

// ---------------------------------------------------------------------------
// Top-k phase B: exact merge of 960 candidates per row by rank-by-broadcast
// under (value desc, global index asc). Emits compact sigmoid'd lists and/or
// a dense zero-filled sigmoid'd row. grid = 8 rows, block = 1024.
// ---------------------------------------------------------------------------
__global__ __launch_bounds__(1024) void topk_merge(
    const float* __restrict__ candv,
    const int*   __restrict__ candi,
    float* __restrict__ vals,     // compact values (or nullptr)
    int*   __restrict__ idxs,     // compact indices (or nullptr)
    float* __restrict__ dense)    // dense zero-filled output (or nullptr)
{
    __shared__ float sv[NCAND];
    __shared__ int   si[NCAND];
    const int row = blockIdx.x;
    const int tid = threadIdx.x;

    if (tid < NCAND) {
        sv[tid] = candv[row * NCAND + tid];
        si[tid] = candi[row * NCAND + tid];
    }
    if (dense) {                               // zero-fill this row
        float4* d4 = reinterpret_cast<float4*>(dense + (size_t)row * DIM);
        for (int q = tid; q < DIM / 4; q += 1024)
            d4[q] = make_float4(0.f, 0.f, 0.f, 0.f);
    }
    __syncthreads();

    if (tid < NCAND) {
        const float v  = sv[tid];
        const int   gi = si[tid];
        int rank = 0;
#pragma unroll 4
        for (int i = 0; i < NCAND; ++i) {
            float u = sv[i];
            rank += (u > v) || (u == v && si[i] < gi);
        }
        if (rank < TOPK) {
            float s = sigmoidf_(v);
            if (vals)  { vals[row * TOPK + rank] = s; idxs[row * TOPK + rank] = gi; }
            if (dense) dense[(size_t)row * DIM + gi] = s;
        }
    }
}

// ---------------------------------------------------------------------------
// GEMM2 (sparse, raw): out[b][j] = sum_s v[b][s] * syn[j][idx[b][s]]
// s-dimension split 4 ways for 4x load parallelism (R4 profile: occ=21%,
// issue=1.1%, DRAM=72% -> latency-starved). Block = (32 j, 8 b, 4 h) = 1024
// threads; each thread gathers 15 elements; SMEM partial-sum reduce.
// Grid = 256 -> single wave, ~55 warps/SM in flight.
// ---------------------------------------------------------------------------
__global__ __launch_bounds__(1024) void gemm2_kernel(
    const float* __restrict__ syn,
    const float* __restrict__ vals,
    const int*   __restrict__ idxs,
    float* __restrict__ out)
{
    __shared__ float sv[BATCH][TOPK];
    __shared__ int   si[BATCH][TOPK];
    __shared__ float part[3][BATCH][32];

    const int tx = threadIdx.x;   // 0..31 (j lane)
    const int b  = threadIdx.y;   // 0..7
    const int h  = threadIdx.z;   // 0..3 (s-split)
    const int t  = (h * 8 + b) * 32 + tx;

    if (t < BATCH * TOPK) {
        int bb = t / TOPK, ss = t % TOPK;
        sv[bb][ss] = vals[bb * TOPK + ss];
        si[bb][ss] = idxs[bb * TOPK + ss];
    }
    __syncthreads();

    const int j = blockIdx.x * 32 + tx;
    const float* __restrict__ wrow = syn + (size_t)j * DIM;
    const int s0 = h * 15;

    float acc = 0.0f;
#pragma unroll
    for (int s = 0; s < 15; ++s)
        acc += sv[b][s0 + s] * __ldg(wrow + si[b][s0 + s]);

    if (h > 0) part[h - 1][b][tx] = acc;
    __syncthreads();
    if (h == 0)
        out[(size_t)b * DIM + j] =
            acc + part[0][b][tx] + part[1][b][tx] + part[2][b][tx];
}

// ---------------------------------------------------------------------------
extern "C" void kernel_launch(void* const* d_in, const int* in_sizes, int n_in,
                              void* d_out, int out_size)
{
    const float* sdr = (const float*)d_in[0];
    const float* syn = (const float*)d_in[1];
    // steps=2, top_k=60 fixed by setup_inputs (hardcoded)

    float *act1, *act2, *candv, *vals;
    int *candi, *idx;
    cudaGetSymbolAddress((void**)&act1,  g_act1);
    cudaGetSymbolAddress((void**)&act2,  g_act2);
    cudaGetSymbolAddress((void**)&candv, g_candv);
    cudaGetSymbolAddress((void**)&candi, g_candi);
    cudaGetSymbolAddress((void**)&vals,  g_vals);
    cudaGetSymbolAddress((void**)&idx,   g_idx);

    // step 1: dense GEMM (raw sums) -> exact top-60 -> compact sigmoid'd lists
    gemm1_kernel<<<DIM / 32, 256>>>(sdr, syn, act1);
    topk_local<<<dim3(SLICES, BATCH), SLICE_LEN>>>(act1, candv, candi);
    topk_merge<<<BATCH, 1024>>>(candv, candi, vals, idx, nullptr);

    // step 2: sparse GEMM (raw sums) -> exact top-60 -> dense sigmoid'd output
    gemm2_kernel<<<DIM / 32, dim3(32, 8, 4)>>>(syn, vals, idx, act2);
    topk_local<<<dim3(SLICES, BATCH), SLICE_LEN>>>(act2, candv, candi);
    topk_merge<<<BATCH, 1024>>>(candv, candi, nullptr, nullptr, (float*)d_out);
}

// round 7
// speedup vs baseline: 2.3914x; 2.2766x over previous
#include <cuda_runtime.h>
#include <cstdint>
#include <cstddef>

#define DIM   8192
#define BATCH 8
#define TOPK  60

// ---------------- scratch (device globals; no allocation allowed) ----------
__device__ float g_act1[BATCH * DIM];
__device__ float g_act2[BATCH * DIM];
__device__ float g_vals[BATCH * 64];
__device__ int   g_idx [BATCH * 64];

typedef unsigned long long u64;

__device__ __forceinline__ void fma2(u64& d, u64 a, u64 b) {
    asm volatile("fma.rn.f32x2 %0, %1, %2, %0;" : "+l"(d) : "l"(a), "l"(b));
}
__device__ __forceinline__ float sigmoidf_(float x) {
    return 1.0f / (1.0f + __expf(-x));
}
__device__ __forceinline__ float pairsum(u64 a) {
    return __uint_as_float((unsigned)(a & 0xffffffffull)) +
           __uint_as_float((unsigned)(a >> 32));
}

// ---------------------------------------------------------------------------
// GEMM1 (raw sums) — R3-proven (≈46 us). 256 threads (8 warps), 4 rows/warp,
// 32-row j-tile, grid = 256. K in 8 chunks of 1024; sdr chunk (32KB) staged
// in SMEM; barrier-free inner loop streams synapse rows; packed f32x2 FMA.
// ---------------------------------------------------------------------------
__global__ __launch_bounds__(256, 2) void gemm1_kernel(
    const float* __restrict__ sdr,
    const float* __restrict__ syn,
    float* __restrict__ out)
{
    __shared__ float4 s_sdr[BATCH * 256];     // 8 x 1024 floats = 32 KB

    const int tid  = threadIdx.x;
    const int warp = tid >> 5;
    const int lane = tid & 31;
    const int jBase = blockIdx.x * 32 + warp * 4;

    const float4* __restrict__ sdr4 = reinterpret_cast<const float4*>(sdr);
    const float4* __restrict__ syn4 = reinterpret_cast<const float4*>(syn);
    const int ROW4 = DIM / 4;                 // 2048 float4 per row

    u64 acc[4][BATCH];
#pragma unroll
    for (int r = 0; r < 4; ++r)
#pragma unroll
        for (int b = 0; b < BATCH; ++b) acc[r][b] = 0ull;

    for (int c = 0; c < 8; ++c) {             // 8 chunks of 1024 floats
        __syncthreads();
#pragma unroll
        for (int u = 0; u < 8; ++u) {
            int e = tid + u * 256;            // 0..2047
            int b = e >> 8, q = e & 255;
            s_sdr[b * 256 + q] = sdr4[(size_t)b * ROW4 + c * 256 + q];
        }
        __syncthreads();

#pragma unroll 2
        for (int it = 0; it < 8; ++it) {      // 256 float4 / 32 lanes
            const int pos = it * 32 + lane;
            float4 w[4];
#pragma unroll
            for (int r = 0; r < 4; ++r)
                w[r] = syn4[(size_t)(jBase + r) * ROW4 + c * 256 + pos];

#pragma unroll
            for (int b = 0; b < BATCH; ++b) {
                float4 s = s_sdr[b * 256 + pos];
                u64 sx = *reinterpret_cast<u64*>(&s.x);
                u64 sz = *reinterpret_cast<u64*>(&s.z);
#pragma unroll
                for (int r = 0; r < 4; ++r) {
                    fma2(acc[r][b], sx, *reinterpret_cast<u64*>(&w[r].x));
                    fma2(acc[r][b], sz, *reinterpret_cast<u64*>(&w[r].z));
                }
            }
        }
    }

#pragma unroll
    for (int r = 0; r < 4; ++r) {
#pragma unroll
        for (int b = 0; b < BATCH; ++b) {
            float v = pairsum(acc[r][b]);
#pragma unroll
            for (int o = 16; o > 0; o >>= 1)
                v += __shfl_xor_sync(0xffffffffu, v, o);
            if (lane == r * 8 + b)
                out[(size_t)b * DIM + jBase + r] = v;
        }
    }
}

// ---------------------------------------------------------------------------
// Exact top-k via 4-pass radix select — R3-proven (≈9.5 us each).
// One block (1024 threads) per row; keys register-resident; warp-private
// histograms; sigmoid applied only on selected outputs (monotone).
// ---------------------------------------------------------------------------
__global__ __launch_bounds__(1024) void topk_kernel(
    const float* __restrict__ act,
    float* __restrict__ dense,     // may be nullptr (zero-filled top-k output)
    float* __restrict__ vals,      // may be nullptr (compact sigmoid'd values)
    int*   __restrict__ idxs)      // may be nullptr
{
    const int row  = blockIdx.x;
    const int tid  = threadIdx.x;
    const int warp = tid >> 5;
    const int lane = tid & 31;
    const float* __restrict__ arow = act + (size_t)row * DIM;

    unsigned key[8];
#pragma unroll
    for (int u = 0; u < 8; ++u) {
        unsigned b = __float_as_uint(arow[tid + u * 1024]);
        key[u] = b ^ (unsigned)(((int)b >> 31) | 0x80000000);
    }

    __shared__ int hist[32][256];            // warp-private, 32 KB
    __shared__ int s_digit, s_kk;

    unsigned prefix = 0;
    int kk = TOPK;

#pragma unroll
    for (int pass = 0; pass < 4; ++pass) {
        const int sh = 24 - pass * 8;
#pragma unroll
        for (int u = 0; u < 8; ++u)
            (&hist[0][0])[tid + u * 1024] = 0;
        __syncthreads();

#pragma unroll
        for (int u = 0; u < 8; ++u) {
            unsigned ky = key[u];
            bool cand = (pass == 0) || ((ky >> (sh + 8)) == prefix);
            if (cand) atomicAdd(&hist[warp][(ky >> sh) & 255], 1);
        }
        __syncthreads();

        if (tid < 256) {
            int s = 0;
#pragma unroll
            for (int w = 0; w < 32; ++w) s += hist[w][tid];
            hist[0][tid] = s;
        }
        __syncthreads();

        if (warp == 0) {
            const int base = 255 - lane * 8;
            int cnt[8]; int local = 0;
#pragma unroll
            for (int j = 0; j < 8; ++j) { cnt[j] = hist[0][base - j]; local += cnt[j]; }
            int incl = local;
#pragma unroll
            for (int o = 1; o < 32; o <<= 1) {
                int v = __shfl_up_sync(0xffffffffu, incl, o);
                if (lane >= o) incl += v;
            }
            const int excl = incl - local;
            if (excl < kk && kk <= incl) {     // exactly one lane
                int run = excl; int found = 0;
#pragma unroll
                for (int j = 0; j < 8; ++j) {
                    if (!found && run + cnt[j] >= kk) {
                        s_digit = base - j;
                        s_kk = kk - run;
                        found = 1;
                    }
                    run += cnt[j];
                }
            }
        }
        __syncthreads();
        prefix = (prefix << 8) | (unsigned)s_digit;
        kk = s_kk;
        __syncthreads();
    }

    const unsigned K = prefix;   // k-th largest transformed key (exact)
    const int rem = kk;          // how many keys == K to keep

    __shared__ int s_pos, s_eq;
    if (tid == 0) { s_pos = 0; s_eq = 0; }
    __syncthreads();

#pragma unroll
    for (int u = 0; u < 8; ++u) {
        const unsigned ky = key[u];
        const int gi = tid + u * 1024;
        bool sel = false;
        if (ky > K) sel = true;
        else if (ky == K) {
            int e = atomicAdd(&s_eq, 1);
            if (e < rem) sel = true;
        }
        float sv = 0.0f;
        if (sel) {
            unsigned b = (ky & 0x80000000u) ? (ky ^ 0x80000000u) : ~ky;
            sv = sigmoidf_(__uint_as_float(b));
            if (vals) {
                int p = atomicAdd(&s_pos, 1);
                vals[row * 64 + p] = sv;
                idxs[row * 64 + p] = gi;
            }
        }
        if (dense) dense[(size_t)row * DIM + gi] = sv;
    }
}

// ---------------------------------------------------------------------------
// GEMM2 (sparse, raw): out[b][j] = sum_s v[b][s] * syn[j][idx[b][s]]
// One warp per (j,b): all 60 gathers land inside the single 32KB row j
// (1-2 DRAM pages per warp burst). Lists padded to 64 with v=0 (branch-free,
// 2 independent loads per lane), 5-step shuffle reduce, lane 0 writes.
// Block = 32 warps; grid = DIM*BATCH/32 = 2048 blocks (FIXED from R6).
// ---------------------------------------------------------------------------
__global__ __launch_bounds__(1024) void gemm2_kernel(
    const float* __restrict__ syn,
    const float* __restrict__ vals,
    const int*   __restrict__ idxs,
    float* __restrict__ out)
{
    __shared__ float sv[BATCH][64];
    __shared__ int   si[BATCH][64];

    const int tid = threadIdx.x;
    if (tid < BATCH * 64) {
        int bb = tid >> 6, ss = tid & 63;
        sv[bb][ss] = (ss < TOPK) ? vals[bb * 64 + ss] : 0.0f;
        si[bb][ss] = (ss < TOPK) ? idxs[bb * 64 + ss] : 0;
    }
    __syncthreads();

    const int warp = tid >> 5;
    const int lane = tid & 31;
    const int gw = blockIdx.x * 32 + warp;   // 0..65535
    const int j  = gw >> 3;                  // 0..8191
    const int b  = gw & 7;

    const float* __restrict__ wrow = syn + (size_t)j * DIM;
    float acc = sv[b][lane]      * __ldg(wrow + si[b][lane])
              + sv[b][lane + 32] * __ldg(wrow + si[b][lane + 32]);

#pragma unroll
    for (int o = 16; o > 0; o >>= 1)
        acc += __shfl_xor_sync(0xffffffffu, acc, o);
    if (lane == 0)
        out[(size_t)b * DIM + j] = acc;
}

// ---------------------------------------------------------------------------
extern "C" void kernel_launch(void* const* d_in, const int* in_sizes, int n_in,
                              void* d_out, int out_size)
{
    const float* sdr = (const float*)d_in[0];
    const float* syn = (const float*)d_in[1];
    // steps=2, top_k=60 fixed by setup_inputs (hardcoded)

    float *act1, *act2, *vals;
    int *idx;
    cudaGetSymbolAddress((void**)&act1, g_act1);
    cudaGetSymbolAddress((void**)&act2, g_act2);
    cudaGetSymbolAddress((void**)&vals, g_vals);
    cudaGetSymbolAddress((void**)&idx,  g_idx);

    // step 1: dense GEMM (raw sums) -> exact top-60 -> compact sigmoid'd lists
    gemm1_kernel<<<DIM / 32, 256>>>(sdr, syn, act1);
    topk_kernel<<<BATCH, 1024>>>(act1, nullptr, vals, idx);
    // step 2: sparse GEMM (raw sums) -> exact top-60 -> dense sigmoid'd output
    // one warp per (j,b): DIM*BATCH = 65536 warps / 32 warps per block = 2048
    gemm2_kernel<<<(DIM * BATCH) / 32, 1024>>>(syn, vals, idx, act2);
    topk_kernel<<<BATCH, 1024>>>(act2, (float*)d_out, nullptr, nullptr);
}

// round 9
// speedup vs baseline: 2.5019x; 1.0462x over previous
#include <cuda_runtime.h>
#include <cstdint>
#include <cstddef>

#define DIM   8192
#define BATCH 8
#define TOPK  60

// ---------------- scratch (device globals; no allocation allowed) ----------
__device__ float g_act1[BATCH * DIM];
__device__ float g_act2[BATCH * DIM];
__device__ float g_vals[BATCH * 64];
__device__ int   g_idx [BATCH * 64];

typedef unsigned long long u64;

__device__ __forceinline__ void fma2(u64& d, u64 a, u64 b) {
    asm volatile("fma.rn.f32x2 %0, %1, %2, %0;" : "+l"(d) : "l"(a), "l"(b));
}
__device__ __forceinline__ float sigmoidf_(float x) {
    return 1.0f / (1.0f + __expf(-x));
}
__device__ __forceinline__ float pairsum(u64 a) {
    return __uint_as_float((unsigned)(a & 0xffffffffull)) +
           __uint_as_float((unsigned)(a >> 32));
}

// ---------------------------------------------------------------------------
// GEMM1 (raw sums): out[b][j] = sum_i sdr[b][i] * syn[j][i]
// R7 structure + 2-stage register prefetch of the synapse tile: 8 LDG.128
// in flight per warp (was 4) to cover the 577-cyc DRAM latency (MLP fix).
// 256 threads (8 warps), 4 rows/warp, 32-row j-tile, grid = 256.
// ---------------------------------------------------------------------------
__global__ __launch_bounds__(256, 2) void gemm1_kernel(
    const float* __restrict__ sdr,
    const float* __restrict__ syn,
    float* __restrict__ out)
{
    __shared__ float4 s_sdr[BATCH * 256];     // 8 x 1024 floats = 32 KB

    const int tid  = threadIdx.x;
    const int warp = tid >> 5;
    const int lane = tid & 31;
    const int jBase = blockIdx.x * 32 + warp * 4;

    const float4* __restrict__ sdr4 = reinterpret_cast<const float4*>(sdr);
    const float4* __restrict__ syn4 = reinterpret_cast<const float4*>(syn);
    const int ROW4 = DIM / 4;                 // 2048 float4 per row

    u64 acc[4][BATCH];
#pragma unroll
    for (int r = 0; r < 4; ++r)
#pragma unroll
        for (int b = 0; b < BATCH; ++b) acc[r][b] = 0ull;

    for (int c = 0; c < 8; ++c) {             // 8 chunks of 1024 floats
        __syncthreads();
#pragma unroll
        for (int u = 0; u < 8; ++u) {
            int e = tid + u * 256;            // 0..2047
            int b = e >> 8, q = e & 255;
            s_sdr[b * 256 + q] = sdr4[(size_t)b * ROW4 + c * 256 + q];
        }
        __syncthreads();

        // prime pipeline: it = 0 loads
        float4 w[4];
#pragma unroll
        for (int r = 0; r < 4; ++r)
            w[r] = syn4[(size_t)(jBase + r) * ROW4 + c * 256 + lane];

#pragma unroll 1
        for (int it = 0; it < 8; ++it) {      // 256 float4 / 32 lanes
            float4 wn[4];
            if (it < 7) {
#pragma unroll
                for (int r = 0; r < 4; ++r)
                    wn[r] = syn4[(size_t)(jBase + r) * ROW4 + c * 256 + (it + 1) * 32 + lane];
            }
            const int pos = it * 32 + lane;
#pragma unroll
            for (int b = 0; b < BATCH; ++b) {
                float4 s = s_sdr[b * 256 + pos];
                u64 sx = *reinterpret_cast<u64*>(&s.x);
                u64 sz = *reinterpret_cast<u64*>(&s.z);
#pragma unroll
                for (int r = 0; r < 4; ++r) {
                    fma2(acc[r][b], sx, *reinterpret_cast<u64*>(&w[r].x));
                    fma2(acc[r][b], sz, *reinterpret_cast<u64*>(&w[r].z));
                }
            }
            if (it < 7) {
#pragma unroll
                for (int r = 0; r < 4; ++r) w[r] = wn[r];
            }
        }
    }

#pragma unroll
    for (int r = 0; r < 4; ++r) {
#pragma unroll
        for (int b = 0; b < BATCH; ++b) {
            float v = pairsum(acc[r][b]);
#pragma unroll
            for (int o = 16; o > 0; o >>= 1)
                v += __shfl_xor_sync(0xffffffffu, v, o);
            if (lane == r * 8 + b)
                out[(size_t)b * DIM + jBase + r] = v;
        }
    }
}

// ---------------------------------------------------------------------------
// Exact top-k: 2-pass radix (16 bits) + direct warp selection among the
// (almost always <=32) candidates sharing the 16-bit prefix; exact fallback
// to radix passes 2-3 if the bin is dense. One block (1024 threads) per row.
// Sigmoid applied only on selected outputs (monotone => same selection).
// ---------------------------------------------------------------------------
__global__ __launch_bounds__(1024) void topk_kernel(
    const float* __restrict__ act,
    float* __restrict__ dense,     // may be nullptr (zero-filled top-k output)
    float* __restrict__ vals,      // may be nullptr (compact sigmoid'd values)
    int*   __restrict__ idxs)      // may be nullptr
{
    const int row  = blockIdx.x;
    const int tid  = threadIdx.x;
    const int warp = tid >> 5;
    const int lane = tid & 31;
    const float* __restrict__ arow = act + (size_t)row * DIM;

    unsigned key[8];
#pragma unroll
    for (int u = 0; u < 8; ++u) {
        unsigned b = __float_as_uint(arow[tid + u * 1024]);
        key[u] = b ^ (unsigned)(((int)b >> 31) | 0x80000000);
    }

    __shared__ int hist[32][256];            // warp-private, 32 KB
    __shared__ int s_digit, s_kk, s_cnt;
    __shared__ int s_np, s_rem;
    __shared__ unsigned s_klow;

    unsigned prefix = 0;
    int kk = TOPK;
    int binCnt = 0;

    // ---- radix passes 0,1 : resolve top 16 bits of the threshold ----
#pragma unroll
    for (int pass = 0; pass < 2; ++pass) {
        const int sh = 24 - pass * 8;
#pragma unroll
        for (int u = 0; u < 8; ++u)
            (&hist[0][0])[tid + u * 1024] = 0;
        __syncthreads();

#pragma unroll
        for (int u = 0; u < 8; ++u) {
            unsigned ky = key[u];
            bool cand = (pass == 0) || ((ky >> (sh + 8)) == prefix);
            if (cand) atomicAdd(&hist[warp][(ky >> sh) & 255], 1);
        }
        __syncthreads();

        if (tid < 256) {
            int s = 0;
#pragma unroll
            for (int w = 0; w < 32; ++w) s += hist[w][tid];
            hist[0][tid] = s;
        }
        __syncthreads();

        if (warp == 0) {
            const int base = 255 - lane * 8;
            int cnt[8]; int local = 0;
#pragma unroll
            for (int j = 0; j < 8; ++j) { cnt[j] = hist[0][base - j]; local += cnt[j]; }
            int incl = local;
#pragma unroll
            for (int o = 1; o < 32; o <<= 1) {
                int v = __shfl_up_sync(0xffffffffu, incl, o);
                if (lane >= o) incl += v;
            }
            const int excl = incl - local;
            if (excl < kk && kk <= incl) {     // exactly one lane
                int run = excl; int found = 0;
#pragma unroll
                for (int j = 0; j < 8; ++j) {
                    if (!found && run + cnt[j] >= kk) {
                        s_digit = base - j;
                        s_kk = kk - run;
                        s_cnt = cnt[j];
                        found = 1;
                    }
                    run += cnt[j];
                }
            }
        }
        __syncthreads();
        prefix = (prefix << 8) | (unsigned)s_digit;
        kk = s_kk;
        binCnt = s_cnt;
        __syncthreads();
    }

    unsigned K;   // exact k-th largest transformed key
    int rem;      // how many keys == K to keep

    if (binCnt <= 32) {
        // ---- direct selection among <=32 candidates sharing prefix16 ----
        if (tid == 0) s_np = 0;
        __syncthreads();
#pragma unroll
        for (int u = 0; u < 8; ++u) {
            if ((key[u] >> 16) == prefix) {
                int p = atomicAdd(&s_np, 1);
                hist[1][p] = (int)(key[u] & 0xffffu);   // reuse smem
            }
        }
        __syncthreads();
        const int np = s_np;                   // == binCnt
        if (warp == 0) {
            int v = (lane < np) ? hist[1][lane] : -1;
            int gt = 0, eq = 0;
#pragma unroll
            for (int j = 0; j < 32; ++j) {
                int vj = __shfl_sync(0xffffffffu, v, j);
                if (j < np) { gt += (vj > v); eq += (vj == v); }   // eq includes self
            }
            if (lane < np && gt < kk && kk <= gt + eq) {
                s_klow = (unsigned)v;          // same v for all qualifying lanes
                s_rem  = kk - gt;
            }
        }
        __syncthreads();
        K = (prefix << 16) | s_klow;
        rem = s_rem;
    } else {
        // ---- fallback: radix passes 2,3 (exact, rare) ----
        for (int pass = 2; pass < 4; ++pass) {
            const int sh = 24 - pass * 8;
#pragma unroll
            for (int u = 0; u < 8; ++u)
                (&hist[0][0])[tid + u * 1024] = 0;
            __syncthreads();

#pragma unroll
            for (int u = 0; u < 8; ++u) {
                unsigned ky = key[u];
                if ((ky >> (sh + 8)) == prefix)
                    atomicAdd(&hist[warp][(ky >> sh) & 255], 1);
            }
            __syncthreads();

            if (tid < 256) {
                int s = 0;
#pragma unroll
                for (int w = 0; w < 32; ++w) s += hist[w][tid];
                hist[0][tid] = s;
            }
            __syncthreads();

            if (warp == 0) {
                const int base = 255 - lane * 8;
                int cnt[8]; int local = 0;
#pragma unroll
                for (int j = 0; j < 8; ++j) { cnt[j] = hist[0][base - j]; local += cnt[j]; }
                int incl = local;
#pragma unroll
                for (int o = 1; o < 32; o <<= 1) {
                    int v = __shfl_up_sync(0xffffffffu, incl, o);
                    if (lane >= o) incl += v;
                }
                const int excl = incl - local;
                if (excl < kk && kk <= incl) {
                    int run = excl; int found = 0;
#pragma unroll
                    for (int j = 0; j < 8; ++j) {
                        if (!found && run + cnt[j] >= kk) {
                            s_digit = base - j;
                            s_kk = kk - run;
                            found = 1;
                        }
                        run += cnt[j];
                    }
                }
            }
            __syncthreads();
            prefix = (prefix << 8) | (unsigned)s_digit;
            kk = s_kk;
            __syncthreads();
        }
        K = prefix;
        rem = kk;
    }

    __shared__ int s_pos, s_eq;
    if (tid == 0) { s_pos = 0; s_eq = 0; }
    __syncthreads();

#pragma unroll
    for (int u = 0; u < 8; ++u) {
        const unsigned ky = key[u];
        const int gi = tid + u * 1024;
        bool sel = false;
        if (ky > K) sel = true;
        else if (ky == K) {
            int e = atomicAdd(&s_eq, 1);
            if (e < rem) sel = true;
        }
        float sv = 0.0f;
        if (sel) {
            unsigned b = (ky & 0x80000000u) ? (ky ^ 0x80000000u) : ~ky;
            sv = sigmoidf_(__uint_as_float(b));
            if (vals) {
                int p = atomicAdd(&s_pos, 1);
                vals[row * 64 + p] = sv;
                idxs[row * 64 + p] = gi;
            }
        }
        if (dense) dense[(size_t)row * DIM + gi] = sv;
    }
}

// ---------------------------------------------------------------------------
// GEMM2 (sparse, raw) — R7-proven (≈42 us, at its DRAM floor).
// One warp per (j,b): all 60 gathers inside the single 32KB row j.
// ---------------------------------------------------------------------------
__global__ __launch_bounds__(1024) void gemm2_kernel(
    const float* __restrict__ syn,
    const float* __restrict__ vals,
    const int*   __restrict__ idxs,
    float* __restrict__ out)
{
    __shared__ float sv[BATCH][64];
    __shared__ int   si[BATCH][64];

    const int tid = threadIdx.x;
    if (tid < BATCH * 64) {
        int bb = tid >> 6, ss = tid & 63;
        sv[bb][ss] = (ss < TOPK) ? vals[bb * 64 + ss] : 0.0f;
        si[bb][ss] = (ss < TOPK) ? idxs[bb * 64 + ss] : 0;
    }
    __syncthreads();

    const int warp = tid >> 5;
    const int lane = tid & 31;
    const int gw = blockIdx.x * 32 + warp;   // 0..65535
    const int j  = gw >> 3;                  // 0..8191
    const int b  = gw & 7;

    const float* __restrict__ wrow = syn + (size_t)j * DIM;
    float acc = sv[b][lane]      * __ldg(wrow + si[b][lane])
              + sv[b][lane + 32] * __ldg(wrow + si[b][lane + 32]);

#pragma unroll
    for (int o = 16; o > 0; o >>= 1)
        acc += __shfl_xor_sync(0xffffffffu, acc, o);
    if (lane == 0)
        out[(size_t)b * DIM + j] = acc;
}

// ---------------------------------------------------------------------------
extern "C" void kernel_launch(void* const* d_in, const int* in_sizes, int n_in,
                              void* d_out, int out_size)
{
    const float* sdr = (const float*)d_in[0];
    const float* syn = (const float*)d_in[1];
    // steps=2, top_k=60 fixed by setup_inputs (hardcoded)

    float *act1, *act2, *vals;
    int *idx;
    cudaGetSymbolAddress((void**)&act1, g_act1);
    cudaGetSymbolAddress((void**)&act2, g_act2);
    cudaGetSymbolAddress((void**)&vals, g_vals);
    cudaGetSymbolAddress((void**)&idx,  g_idx);

    // step 1: dense GEMM (raw sums) -> exact top-60 -> compact sigmoid'd lists
    gemm1_kernel<<<DIM / 32, 256>>>(sdr, syn, act1);
    topk_kernel<<<BATCH, 1024>>>(act1, nullptr, vals, idx);
    // step 2: sparse GEMM (raw sums) -> exact top-60 -> dense sigmoid'd output
    gemm2_kernel<<<(DIM * BATCH) / 32, 1024>>>(syn, vals, idx, act2);
    topk_kernel<<<BATCH, 1024>>>(act2, (float*)d_out, nullptr, nullptr);
}